// round 10
// baseline (speedup 1.0000x reference)
#include <cuda_runtime.h>
#include <cuda_bf16.h>
#include <math.h>

// 3-layer GCN, N=50000, E=800000, dims 128->64->64->32.
// Layer: out[d] = dis[d]*( sum_{s->d} dis[s]*h[s] + dis[d]*h[d] ) + b, h = in@W
// CSR-by-dst gather. CSR build on forked stream concurrent with gemm1.
// Layers software-pipelined across two streams in node-halves:
//   0:  g1a -> gemm2a ............ g2a -> gemm3a ...... g3
//   s2: ......... g1b -> gemm2b ......... g2b -> gemm3b
// (gemm_{l+1} half-X depends only on gather_l half-X; gather_{l+1} needs both.)

#define NMAX 50000
#define EMAX 800000

__device__ float g_hs1[NMAX * 64];   // gemm1 out (unscaled); reused for gemm3 out
__device__ float g_hs2[NMAX * 64];   // gemm2 out (pre-scaled)
__device__ float g_hA [NMAX * 64];   // layer-1 activations
__device__ float g_hB [NMAX * 64];   // layer-2 activations
__device__ float g_dis[NMAX];
__device__ int   g_deg[NMAX];
__device__ int   g_scan[NMAX];
__device__ int   g_bsum[64];
__device__ int   g_rowptr[NMAX + 1];
__device__ int   g_cursor[NMAX];
__device__ int   g_col[EMAX];

// ---------------------------------------------------------------------------
// packed f32x2 helpers (sm_103a)
// ---------------------------------------------------------------------------
__device__ __forceinline__ unsigned long long pack2(float a, float b) {
    unsigned long long r;
    asm("mov.b64 %0, {%1, %2};" : "=l"(r) : "f"(a), "f"(b));
    return r;
}
__device__ __forceinline__ unsigned long long ffma2(unsigned long long a,
                                                    unsigned long long b,
                                                    unsigned long long c) {
    unsigned long long d;
    asm("fma.rn.f32x2 %0, %1, %2, %3;" : "=l"(d) : "l"(a), "l"(b), "l"(c));
    return d;
}
__device__ __forceinline__ unsigned long long fmul2(unsigned long long a,
                                                    unsigned long long b) {
    unsigned long long d;
    asm("mul.rn.f32x2 %0, %1, %2;" : "=l"(d) : "l"(a), "l"(b));
    return d;
}

// ---------------------------------------------------------------------------
// CSR build
// ---------------------------------------------------------------------------
__global__ void deg_count_kernel(const int* __restrict__ dst, int* deg, int e) {
    int q = blockIdx.x * blockDim.x + threadIdx.x;
    int base = q * 4;
    if (base + 4 <= e) {
        int4 d4 = *reinterpret_cast<const int4*>(dst + base);
        atomicAdd(&deg[d4.x], 1);
        atomicAdd(&deg[d4.y], 1);
        atomicAdd(&deg[d4.z], 1);
        atomicAdd(&deg[d4.w], 1);
    } else {
        for (int i = base; i < e; i++) atomicAdd(&deg[dst[i]], 1);
    }
}

__global__ void scan1_kernel(const int* __restrict__ deg, int* scanout,
                             int* bsum, int n) {
    __shared__ int s[1024];
    int i = blockIdx.x * 1024 + threadIdx.x;
    int v = (i < n) ? deg[i] : 0;
    s[threadIdx.x] = v;
    __syncthreads();
#pragma unroll
    for (int off = 1; off < 1024; off <<= 1) {
        int add = (threadIdx.x >= off) ? s[threadIdx.x - off] : 0;
        __syncthreads();
        s[threadIdx.x] += add;
        __syncthreads();
    }
    if (i < n) scanout[i] = s[threadIdx.x];
    if (threadIdx.x == 1023) bsum[blockIdx.x] = s[1023];
}

// Fixup with inlined bsum-prefix (each 256-thread block lies in one 1024-tile).
__global__ void fixup_kernel(const int* __restrict__ scanin,
                             const int* __restrict__ deg,
                             const int* __restrict__ bsum,
                             int* rowptr, int* cursor, float* dis,
                             int n, int e) {
    __shared__ int wsum[8];
    int tile = blockIdx.x >> 2;
    int part = 0;
    for (int j = threadIdx.x; j < tile; j += blockDim.x) part += bsum[j];
#pragma unroll
    for (int off = 16; off > 0; off >>= 1)
        part += __shfl_down_sync(0xFFFFFFFFu, part, off);
    if ((threadIdx.x & 31) == 0) wsum[threadIdx.x >> 5] = part;
    __syncthreads();
    if (threadIdx.x == 0) {
        int b = 0;
#pragma unroll
        for (int w = 0; w < 8; w++) b += wsum[w];
        wsum[0] = b;
    }
    __syncthreads();
    int base = wsum[0];

    int i = blockIdx.x * blockDim.x + threadIdx.x;
    if (i < n) {
        int d = deg[i];
        int rp = scanin[i] - d + base;
        rowptr[i] = rp;
        cursor[i] = rp;
        dis[i] = rsqrtf((float)(d + 1));  // +1 self loop
    }
    if (i == 0) rowptr[n] = e;
}

__global__ void fill_kernel(const int* __restrict__ src,
                            const int* __restrict__ dst,
                            int* cursor, int* col, int e) {
    int q = blockIdx.x * blockDim.x + threadIdx.x;
    int base = q * 4;
    if (base + 4 <= e) {
        int4 s4 = *reinterpret_cast<const int4*>(src + base);
        int4 d4 = *reinterpret_cast<const int4*>(dst + base);
        int p0 = atomicAdd(&cursor[d4.x], 1);
        int p1 = atomicAdd(&cursor[d4.y], 1);
        int p2 = atomicAdd(&cursor[d4.z], 1);
        int p3 = atomicAdd(&cursor[d4.w], 1);
        col[p0] = s4.x;
        col[p1] = s4.y;
        col[p2] = s4.z;
        col[p3] = s4.w;
    } else {
        for (int i = base; i < e; i++) {
            int p = atomicAdd(&cursor[dst[i]], 1);
            col[p] = src[i];
        }
    }
}

// ---------------------------------------------------------------------------
// GEMM over row range [row0, row1): hs[row,:] = (in[row,:] @ W) * (dis?[row])
// ---------------------------------------------------------------------------
template <int IN, int OUT, bool PRESCALE>
__global__ void gemm_kernel(const float* __restrict__ in,
                            const float* __restrict__ W,
                            const float* __restrict__ dis,
                            float* __restrict__ hs, int row0, int row1) {
    __shared__ __align__(16) float sW[IN * OUT];
    for (int i = threadIdx.x; i < IN * OUT / 4; i += blockDim.x)
        reinterpret_cast<float4*>(sW)[i] = reinterpret_cast<const float4*>(W)[i];
    __syncthreads();

    int row = row0 + blockIdx.x * blockDim.x + threadIdx.x;
    if (row >= row1) return;

    unsigned long long acc[OUT / 2];
#pragma unroll
    for (int c = 0; c < OUT / 2; c++) acc[c] = 0ULL;

    const float* xr = in + (size_t)row * IN;
    for (int k0 = 0; k0 < IN; k0 += 4) {
        float4 xv = *reinterpret_cast<const float4*>(xr + k0);
        float xs[4] = {xv.x, xv.y, xv.z, xv.w};
#pragma unroll
        for (int kk = 0; kk < 4; kk++) {
            unsigned long long xx = pack2(xs[kk], xs[kk]);
            const ulonglong2* wr =
                reinterpret_cast<const ulonglong2*>(sW + (k0 + kk) * OUT);
#pragma unroll
            for (int c4 = 0; c4 < OUT / 4; c4++) {
                ulonglong2 w = wr[c4];
                acc[c4 * 2 + 0] = ffma2(xx, w.x, acc[c4 * 2 + 0]);
                acc[c4 * 2 + 1] = ffma2(xx, w.y, acc[c4 * 2 + 1]);
            }
        }
    }

    ulonglong2* hp = reinterpret_cast<ulonglong2*>(hs + (size_t)row * OUT);
    if (PRESCALE) {
        float d = dis[row];
        unsigned long long dd = pack2(d, d);
#pragma unroll
        for (int c4 = 0; c4 < OUT / 4; c4++) {
            ulonglong2 r;
            r.x = fmul2(acc[c4 * 2 + 0], dd);
            r.y = fmul2(acc[c4 * 2 + 1], dd);
            hp[c4] = r;
        }
    } else {
#pragma unroll
        for (int c4 = 0; c4 < OUT / 4; c4++) {
            ulonglong2 r;
            r.x = acc[c4 * 2 + 0];
            r.y = acc[c4 * 2 + 1];
            hp[c4] = r;
        }
    }
}

// ---------------------------------------------------------------------------
// Gather + finalize over node range [n0, n1).
// DIS_SRC: hs unscaled -> multiply gathered values by dis[src] (layer 1).
// out[d,:] = [relu]( dis[d]*acc + b )
// ---------------------------------------------------------------------------
template <int OUT, bool RELU, bool DIS_SRC>
__global__ void gather_kernel(const int* __restrict__ rowptr,
                              const int* __restrict__ col,
                              const float* __restrict__ hs,
                              const float* __restrict__ dis,
                              const float* __restrict__ bias,
                              float* __restrict__ out, int n0, int n1) {
    const int G = OUT / 4;
    int t = blockIdx.x * blockDim.x + threadIdx.x;
    int gid = n0 + t / G;
    int lane = t % G;
    if (gid >= n1) return;

    const float4* hs4 = reinterpret_cast<const float4*>(hs);
    int beg = rowptr[gid];
    int end = rowptr[gid + 1];

    float dself = dis[gid];
    float4 a0 = hs4[(size_t)gid * G + lane];  // self term
    if (DIS_SRC) {
        a0.x *= dself; a0.y *= dself; a0.z *= dself; a0.w *= dself;
    }

#pragma unroll 4
    for (int e = beg; e < end; e++) {
        int s = __ldg(&col[e]);
        float4 v = hs4[(size_t)s * G + lane];
        if (DIS_SRC) {
            float ds = __ldg(&dis[s]);
            a0.x += v.x * ds; a0.y += v.y * ds;
            a0.z += v.z * ds; a0.w += v.w * ds;
        } else {
            a0.x += v.x; a0.y += v.y; a0.z += v.z; a0.w += v.w;
        }
    }

    float4 b4 = reinterpret_cast<const float4*>(bias)[lane];
    float4 r;
    r.x = a0.x * dself + b4.x;
    r.y = a0.y * dself + b4.y;
    r.z = a0.z * dself + b4.z;
    r.w = a0.w * dself + b4.w;
    if (RELU) {
        r.x = fmaxf(r.x, 0.0f);
        r.y = fmaxf(r.y, 0.0f);
        r.z = fmaxf(r.z, 0.0f);
        r.w = fmaxf(r.w, 0.0f);
    }
    reinterpret_cast<float4*>(out)[(size_t)gid * G + lane] = r;
}

// ---------------------------------------------------------------------------
// launch
// ---------------------------------------------------------------------------
extern "C" void kernel_launch(void* const* d_in, const int* in_sizes, int n_in,
                              void* d_out, int out_size) {
    const float* x    = (const float*)d_in[0];
    const int*   eidx = (const int*)  d_in[1];
    const float* W1   = (const float*)d_in[2];
    const float* b1   = (const float*)d_in[3];
    const float* W2   = (const float*)d_in[4];
    const float* b2   = (const float*)d_in[5];
    const float* W3   = (const float*)d_in[6];
    const float* b3   = (const float*)d_in[7];

    const int N = in_sizes[0] / 128;
    const int E = in_sizes[1] / 2;
    const int* esrc = eidx;
    const int* edst = eidx + E;

    float *hs1, *hs2, *hA, *hB, *dis;
    int *deg, *scn, *bsum, *rowptr, *cursor, *col;
    cudaGetSymbolAddress((void**)&hs1,    g_hs1);
    cudaGetSymbolAddress((void**)&hs2,    g_hs2);
    cudaGetSymbolAddress((void**)&hA,     g_hA);
    cudaGetSymbolAddress((void**)&hB,     g_hB);
    cudaGetSymbolAddress((void**)&dis,    g_dis);
    cudaGetSymbolAddress((void**)&deg,    g_deg);
    cudaGetSymbolAddress((void**)&scn,    g_scan);
    cudaGetSymbolAddress((void**)&bsum,   g_bsum);
    cudaGetSymbolAddress((void**)&rowptr, g_rowptr);
    cudaGetSymbolAddress((void**)&cursor, g_cursor);
    cudaGetSymbolAddress((void**)&col,    g_col);

    float* out = (float*)d_out;
    const int T = 256;
    const int NB = (N + 1023) / 1024;
    const int EQ = (E + 3) / 4;
    const int Nh = N / 2;               // node split for the pipeline
    const int Ra = Nh, Rb = N - Nh;     // half sizes

    cudaStream_t s2;
    cudaEvent_t evFork, evCSR, evG1a, evL2b, evG2a, evL3b;
    cudaStreamCreateWithFlags(&s2, cudaStreamNonBlocking);
    cudaEventCreateWithFlags(&evFork, cudaEventDisableTiming);
    cudaEventCreateWithFlags(&evCSR,  cudaEventDisableTiming);
    cudaEventCreateWithFlags(&evG1a,  cudaEventDisableTiming);
    cudaEventCreateWithFlags(&evL2b,  cudaEventDisableTiming);
    cudaEventCreateWithFlags(&evG2a,  cudaEventDisableTiming);
    cudaEventCreateWithFlags(&evL3b,  cudaEventDisableTiming);

    cudaEventRecord(evFork, 0);
    cudaStreamWaitEvent(s2, evFork, 0);

    // --- CSR build on s2, concurrent with gemm1 on stream 0 ---
    cudaMemsetAsync(deg, 0, (size_t)N * sizeof(int), s2);
    deg_count_kernel<<<(EQ + T - 1) / T, T, 0, s2>>>(edst, deg, E);
    scan1_kernel    <<<NB, 1024, 0, s2>>>(deg, scn, bsum, N);
    fixup_kernel    <<<(N + T - 1) / T, T, 0, s2>>>(scn, deg, bsum,
                                                    rowptr, cursor, dis, N, E);
    fill_kernel     <<<(EQ + T - 1) / T, T, 0, s2>>>(esrc, edst, cursor, col, E);
    cudaEventRecord(evCSR, s2);

    // --- gemm1 (full, dis-free) on stream 0 ---
    gemm_kernel<128, 64, false><<<(N + 127) / 128, 128>>>(x, W1, nullptr, hs1, 0, N);
    cudaStreamWaitEvent(0, evCSR, 0);

    // ===== layer-1 gather / layer-2 gemm, pipelined halves =====
    gather_kernel<64, true, true><<<(Ra * 16 + T - 1) / T, T>>>(
        rowptr, col, hs1, dis, b1, hA, 0, Nh);
    cudaEventRecord(evG1a, 0);

    // s2: second half of gather1, then its gemm2 half (overlaps gemm2a on 0)
    cudaStreamWaitEvent(s2, evG1a, 0);
    gather_kernel<64, true, true><<<(Rb * 16 + T - 1) / T, T, 0, s2>>>(
        rowptr, col, hs1, dis, b1, hA, Nh, N);
    gemm_kernel<64, 64, true><<<(Rb + 127) / 128, 128, 0, s2>>>(
        hA, W2, dis, hs2, Nh, N);
    cudaEventRecord(evL2b, s2);

    // 0: first-half gemm2 (concurrent with g1b on s2)
    gemm_kernel<64, 64, true><<<(Ra + 127) / 128, 128>>>(hA, W2, dis, hs2, 0, Nh);
    cudaStreamWaitEvent(0, evL2b, 0);

    // ===== layer-2 gather / layer-3 gemm, pipelined halves =====
    gather_kernel<64, true, false><<<(Ra * 16 + T - 1) / T, T>>>(
        rowptr, col, hs2, dis, b2, hB, 0, Nh);
    cudaEventRecord(evG2a, 0);

    cudaStreamWaitEvent(s2, evG2a, 0);
    gather_kernel<64, true, false><<<(Rb * 16 + T - 1) / T, T, 0, s2>>>(
        rowptr, col, hs2, dis, b2, hB, Nh, N);
    gemm_kernel<64, 32, true><<<(Rb + 127) / 128, 128, 0, s2>>>(
        hB, W3, dis, hs1, Nh, N);
    cudaEventRecord(evL3b, s2);

    gemm_kernel<64, 32, true><<<(Ra + 127) / 128, 128>>>(hB, W3, dis, hs1, 0, Nh);
    cudaStreamWaitEvent(0, evL3b, 0);

    // ===== layer-3 gather (full) =====
    gather_kernel<32, false, false><<<(N * 8 + T - 1) / T, T>>>(
        rowptr, col, hs1, dis, b3, out, 0, N);

    cudaEventDestroy(evFork);
    cudaEventDestroy(evCSR);
    cudaEventDestroy(evG1a);
    cudaEventDestroy(evL2b);
    cudaEventDestroy(evG2a);
    cudaEventDestroy(evL3b);
    cudaStreamDestroy(s2);
}

// round 11
// speedup vs baseline: 1.1467x; 1.1467x over previous
#include <cuda_runtime.h>
#include <cuda_bf16.h>
#include <math.h>

// 3-layer GCN, N=50000, E=800000, dims 128->64->64->32.
// Layer: out[d] = dis[d]*( sum_{s->d} dis[s]*h[s] + dis[d]*h[d] ) + b, h = in@W
// CSR-by-dst gather; CSR build on forked stream concurrent with gemm1.
// Boundary GEMMs fused into the gathers (gather1+gemm2, gather2+gemm3):
// gather result lives in shared, GEMM row computed in-block, hA/hB never
// touch global memory.

#define NMAX 50000
#define EMAX 800000

__device__ float g_hs1[NMAX * 64];   // gemm1 out (unscaled)
__device__ float g_hs2[NMAX * 64];   // fused1 out (pre-scaled h2)
__device__ float g_hs3[NMAX * 64];   // fused2 out (pre-scaled h3)
__device__ float g_dis[NMAX];
__device__ int   g_deg[NMAX];
__device__ int   g_scan[NMAX];
__device__ int   g_bsum[64];
__device__ int   g_rowptr[NMAX + 1];
__device__ int   g_cursor[NMAX];
__device__ int   g_col[EMAX];

// ---------------------------------------------------------------------------
// packed f32x2 helpers (sm_103a)
// ---------------------------------------------------------------------------
__device__ __forceinline__ unsigned long long pack2(float a, float b) {
    unsigned long long r;
    asm("mov.b64 %0, {%1, %2};" : "=l"(r) : "f"(a), "f"(b));
    return r;
}
__device__ __forceinline__ unsigned long long ffma2(unsigned long long a,
                                                    unsigned long long b,
                                                    unsigned long long c) {
    unsigned long long d;
    asm("fma.rn.f32x2 %0, %1, %2, %3;" : "=l"(d) : "l"(a), "l"(b), "l"(c));
    return d;
}
__device__ __forceinline__ unsigned long long fmul2(unsigned long long a,
                                                    unsigned long long b) {
    unsigned long long d;
    asm("mul.rn.f32x2 %0, %1, %2;" : "=l"(d) : "l"(a), "l"(b));
    return d;
}
__device__ __forceinline__ void unpack2(unsigned long long v, float& lo, float& hi) {
    asm("mov.b64 {%0, %1}, %2;" : "=f"(lo), "=f"(hi) : "l"(v));
}

// ---------------------------------------------------------------------------
// CSR build
// ---------------------------------------------------------------------------
__global__ void deg_count_kernel(const int* __restrict__ dst, int* deg, int e) {
    int q = blockIdx.x * blockDim.x + threadIdx.x;
    int base = q * 4;
    if (base + 4 <= e) {
        int4 d4 = *reinterpret_cast<const int4*>(dst + base);
        atomicAdd(&deg[d4.x], 1);
        atomicAdd(&deg[d4.y], 1);
        atomicAdd(&deg[d4.z], 1);
        atomicAdd(&deg[d4.w], 1);
    } else {
        for (int i = base; i < e; i++) atomicAdd(&deg[dst[i]], 1);
    }
}

__global__ void scan1_kernel(const int* __restrict__ deg, int* scanout,
                             int* bsum, int n) {
    __shared__ int s[1024];
    int i = blockIdx.x * 1024 + threadIdx.x;
    int v = (i < n) ? deg[i] : 0;
    s[threadIdx.x] = v;
    __syncthreads();
#pragma unroll
    for (int off = 1; off < 1024; off <<= 1) {
        int add = (threadIdx.x >= off) ? s[threadIdx.x - off] : 0;
        __syncthreads();
        s[threadIdx.x] += add;
        __syncthreads();
    }
    if (i < n) scanout[i] = s[threadIdx.x];
    if (threadIdx.x == 1023) bsum[blockIdx.x] = s[1023];
}

// Fixup with inlined bsum-prefix (each 256-thread block lies in one 1024-tile).
__global__ void fixup_kernel(const int* __restrict__ scanin,
                             const int* __restrict__ deg,
                             const int* __restrict__ bsum,
                             int* rowptr, int* cursor, float* dis,
                             int n, int e) {
    __shared__ int wsum[8];
    int tile = blockIdx.x >> 2;
    int part = 0;
    for (int j = threadIdx.x; j < tile; j += blockDim.x) part += bsum[j];
#pragma unroll
    for (int off = 16; off > 0; off >>= 1)
        part += __shfl_down_sync(0xFFFFFFFFu, part, off);
    if ((threadIdx.x & 31) == 0) wsum[threadIdx.x >> 5] = part;
    __syncthreads();
    if (threadIdx.x == 0) {
        int b = 0;
#pragma unroll
        for (int w = 0; w < 8; w++) b += wsum[w];
        wsum[0] = b;
    }
    __syncthreads();
    int base = wsum[0];

    int i = blockIdx.x * blockDim.x + threadIdx.x;
    if (i < n) {
        int d = deg[i];
        int rp = scanin[i] - d + base;
        rowptr[i] = rp;
        cursor[i] = rp;
        dis[i] = rsqrtf((float)(d + 1));  // +1 self loop
    }
    if (i == 0) rowptr[n] = e;
}

__global__ void fill_kernel(const int* __restrict__ src,
                            const int* __restrict__ dst,
                            int* cursor, int* col, int e) {
    int q = blockIdx.x * blockDim.x + threadIdx.x;
    int base = q * 4;
    if (base + 4 <= e) {
        int4 s4 = *reinterpret_cast<const int4*>(src + base);
        int4 d4 = *reinterpret_cast<const int4*>(dst + base);
        int p0 = atomicAdd(&cursor[d4.x], 1);
        int p1 = atomicAdd(&cursor[d4.y], 1);
        int p2 = atomicAdd(&cursor[d4.z], 1);
        int p3 = atomicAdd(&cursor[d4.w], 1);
        col[p0] = s4.x;
        col[p1] = s4.y;
        col[p2] = s4.z;
        col[p3] = s4.w;
    } else {
        for (int i = base; i < e; i++) {
            int p = atomicAdd(&cursor[dst[i]], 1);
            col[p] = src[i];
        }
    }
}

// ---------------------------------------------------------------------------
// GEMM: hs[row,:] = in[row,:] @ W (layer 1, no dis needed -> overlaps CSR)
// ---------------------------------------------------------------------------
template <int IN, int OUT>
__global__ void gemm_kernel(const float* __restrict__ in,
                            const float* __restrict__ W,
                            float* __restrict__ hs, int n) {
    __shared__ __align__(16) float sW[IN * OUT];
    for (int i = threadIdx.x; i < IN * OUT / 4; i += blockDim.x)
        reinterpret_cast<float4*>(sW)[i] = reinterpret_cast<const float4*>(W)[i];
    __syncthreads();

    int row = blockIdx.x * blockDim.x + threadIdx.x;
    if (row >= n) return;

    unsigned long long acc[OUT / 2];
#pragma unroll
    for (int c = 0; c < OUT / 2; c++) acc[c] = 0ULL;

    const float* xr = in + (size_t)row * IN;
    for (int k0 = 0; k0 < IN; k0 += 4) {
        float4 xv = *reinterpret_cast<const float4*>(xr + k0);
        float xs[4] = {xv.x, xv.y, xv.z, xv.w};
#pragma unroll
        for (int kk = 0; kk < 4; kk++) {
            unsigned long long xx = pack2(xs[kk], xs[kk]);
            const ulonglong2* wr =
                reinterpret_cast<const ulonglong2*>(sW + (k0 + kk) * OUT);
#pragma unroll
            for (int c4 = 0; c4 < OUT / 4; c4++) {
                ulonglong2 w = wr[c4];
                acc[c4 * 2 + 0] = ffma2(xx, w.x, acc[c4 * 2 + 0]);
                acc[c4 * 2 + 1] = ffma2(xx, w.y, acc[c4 * 2 + 1]);
            }
        }
    }

    ulonglong2* hp = reinterpret_cast<ulonglong2*>(hs + (size_t)row * OUT);
#pragma unroll
    for (int c4 = 0; c4 < OUT / 4; c4++) {
        ulonglong2 r;
        r.x = acc[c4 * 2 + 0];
        r.y = acc[c4 * 2 + 1];
        hp[c4] = r;
    }
}

// ---------------------------------------------------------------------------
// Fused gather + GEMM boundary kernel.
//   DIN=64 gather width, DOUT = next-layer out (64 or 32).
//   Phase 1: a[node,:] = relu( dis[d]*(sum dis?[s]*hs[s,:] + self) + bias )
//            -> shared sH
//   Phase 2: hs_out[node,:] = (a[node,:] @ W) * dis[node]   (pre-scaled)
// Block: 16 nodes x 16 lanes = 256 threads.
// ---------------------------------------------------------------------------
template <int DOUT, bool DIS_SRC>
__global__ void gather_gemm_kernel(const int* __restrict__ rowptr,
                                   const int* __restrict__ col,
                                   const float* __restrict__ hs,
                                   const float* __restrict__ dis,
                                   const float* __restrict__ bias,
                                   const float* __restrict__ W,   // [64][DOUT]
                                   float* __restrict__ hs_out, int n) {
    const int DIN = 64;
    const int G = DIN / 4;          // 16 lanes per node
    const int NPB = 256 / G;        // 16 nodes per block
    const int HST = DIN + 4;        // padded sH stride (bank-conflict-free)

    __shared__ __align__(16) float sW[DIN * DOUT];
    __shared__ float sH[NPB * HST];

    for (int i = threadIdx.x; i < DIN * DOUT / 4; i += blockDim.x)
        reinterpret_cast<float4*>(sW)[i] = reinterpret_cast<const float4*>(W)[i];

    int tid = threadIdx.x;
    int ln = tid / G;               // local node
    int lane = tid % G;
    int gid = blockIdx.x * NPB + ln;
    bool valid = (gid < n);

    float dself = 0.0f;

    // ---- phase 1: gather ----
    if (valid) {
        const float4* hs4 = reinterpret_cast<const float4*>(hs);
        int beg = rowptr[gid];
        int end = rowptr[gid + 1];
        dself = dis[gid];

        float4 a0 = hs4[(size_t)gid * G + lane];  // self term
        if (DIS_SRC) {
            a0.x *= dself; a0.y *= dself; a0.z *= dself; a0.w *= dself;
        }
#pragma unroll 4
        for (int e = beg; e < end; e++) {
            int s = __ldg(&col[e]);
            float4 v = hs4[(size_t)s * G + lane];
            if (DIS_SRC) {
                float ds = __ldg(&dis[s]);
                a0.x += v.x * ds; a0.y += v.y * ds;
                a0.z += v.z * ds; a0.w += v.w * ds;
            } else {
                a0.x += v.x; a0.y += v.y; a0.z += v.z; a0.w += v.w;
            }
        }
        float4 b4 = reinterpret_cast<const float4*>(bias)[lane];
        // activation (relu) for this boundary
        float* hrow = sH + ln * HST + lane * 4;
        hrow[0] = fmaxf(a0.x * dself + b4.x, 0.0f);
        hrow[1] = fmaxf(a0.y * dself + b4.y, 0.0f);
        hrow[2] = fmaxf(a0.z * dself + b4.z, 0.0f);
        hrow[3] = fmaxf(a0.w * dself + b4.w, 0.0f);
    }
    __syncthreads();

    // ---- phase 2: GEMM row from shared ----
    if (!valid) return;
    const float* hrow = sH + ln * HST;

    if (DOUT == 64) {
        int c0 = lane * 4;
        unsigned long long acc0 = 0ULL, acc1 = 0ULL;
#pragma unroll 8
        for (int k = 0; k < DIN; k++) {
            float h = hrow[k];
            unsigned long long hh = pack2(h, h);
            const ulonglong2 w =
                *reinterpret_cast<const ulonglong2*>(sW + k * DOUT + c0);
            acc0 = ffma2(hh, w.x, acc0);
            acc1 = ffma2(hh, w.y, acc1);
        }
        unsigned long long dd = pack2(dself, dself);
        ulonglong2 r;
        r.x = fmul2(acc0, dd);
        r.y = fmul2(acc1, dd);
        *reinterpret_cast<ulonglong2*>(hs_out + (size_t)gid * DOUT + c0) = r;
    } else {  // DOUT == 32
        int c0 = lane * 2;
        unsigned long long acc0 = 0ULL;
#pragma unroll 8
        for (int k = 0; k < DIN; k++) {
            float h = hrow[k];
            unsigned long long hh = pack2(h, h);
            const unsigned long long w =
                *reinterpret_cast<const unsigned long long*>(sW + k * DOUT + c0);
            acc0 = ffma2(hh, w, acc0);
        }
        unsigned long long dd = pack2(dself, dself);
        *reinterpret_cast<unsigned long long*>(hs_out + (size_t)gid * DOUT + c0) =
            fmul2(acc0, dd);
    }
}

// ---------------------------------------------------------------------------
// Final gather (layer 3): out[d,:] = dis[d]*acc + b   (hs pre-scaled, no relu)
// ---------------------------------------------------------------------------
template <int OUT>
__global__ void gather_kernel(const int* __restrict__ rowptr,
                              const int* __restrict__ col,
                              const float* __restrict__ hs,
                              const float* __restrict__ dis,
                              const float* __restrict__ bias,
                              float* __restrict__ out, int n) {
    const int G = OUT / 4;
    int t = blockIdx.x * blockDim.x + threadIdx.x;
    int gid = t / G;
    int lane = t % G;
    if (gid >= n) return;

    const float4* hs4 = reinterpret_cast<const float4*>(hs);
    int beg = rowptr[gid];
    int end = rowptr[gid + 1];

    float dself = dis[gid];
    float4 a0 = hs4[(size_t)gid * G + lane];  // self term

#pragma unroll 4
    for (int e = beg; e < end; e++) {
        int s = __ldg(&col[e]);
        float4 v = hs4[(size_t)s * G + lane];
        a0.x += v.x; a0.y += v.y; a0.z += v.z; a0.w += v.w;
    }

    float4 b4 = reinterpret_cast<const float4*>(bias)[lane];
    float4 r;
    r.x = a0.x * dself + b4.x;
    r.y = a0.y * dself + b4.y;
    r.z = a0.z * dself + b4.z;
    r.w = a0.w * dself + b4.w;
    reinterpret_cast<float4*>(out)[(size_t)gid * G + lane] = r;
}

// ---------------------------------------------------------------------------
// launch
// ---------------------------------------------------------------------------
extern "C" void kernel_launch(void* const* d_in, const int* in_sizes, int n_in,
                              void* d_out, int out_size) {
    const float* x    = (const float*)d_in[0];
    const int*   eidx = (const int*)  d_in[1];
    const float* W1   = (const float*)d_in[2];
    const float* b1   = (const float*)d_in[3];
    const float* W2   = (const float*)d_in[4];
    const float* b2   = (const float*)d_in[5];
    const float* W3   = (const float*)d_in[6];
    const float* b3   = (const float*)d_in[7];

    const int N = in_sizes[0] / 128;
    const int E = in_sizes[1] / 2;
    const int* esrc = eidx;
    const int* edst = eidx + E;

    float *hs1, *hs2, *hs3, *dis;
    int *deg, *scn, *bsum, *rowptr, *cursor, *col;
    cudaGetSymbolAddress((void**)&hs1,    g_hs1);
    cudaGetSymbolAddress((void**)&hs2,    g_hs2);
    cudaGetSymbolAddress((void**)&hs3,    g_hs3);
    cudaGetSymbolAddress((void**)&dis,    g_dis);
    cudaGetSymbolAddress((void**)&deg,    g_deg);
    cudaGetSymbolAddress((void**)&scn,    g_scan);
    cudaGetSymbolAddress((void**)&bsum,   g_bsum);
    cudaGetSymbolAddress((void**)&rowptr, g_rowptr);
    cudaGetSymbolAddress((void**)&cursor, g_cursor);
    cudaGetSymbolAddress((void**)&col,    g_col);

    float* out = (float*)d_out;
    const int T = 256;
    const int NB = (N + 1023) / 1024;
    const int EQ = (E + 3) / 4;
    const int NPB = 16;  // nodes per fused block

    cudaStream_t s2;
    cudaEvent_t evFork, evCSR;
    cudaStreamCreateWithFlags(&s2, cudaStreamNonBlocking);
    cudaEventCreateWithFlags(&evFork, cudaEventDisableTiming);
    cudaEventCreateWithFlags(&evCSR,  cudaEventDisableTiming);

    cudaEventRecord(evFork, 0);
    cudaStreamWaitEvent(s2, evFork, 0);

    // --- CSR build on s2, concurrent with gemm1 on stream 0 ---
    cudaMemsetAsync(deg, 0, (size_t)N * sizeof(int), s2);
    deg_count_kernel<<<(EQ + T - 1) / T, T, 0, s2>>>(edst, deg, E);
    scan1_kernel    <<<NB, 1024, 0, s2>>>(deg, scn, bsum, N);
    fixup_kernel    <<<(N + T - 1) / T, T, 0, s2>>>(scn, deg, bsum,
                                                    rowptr, cursor, dis, N, E);
    fill_kernel     <<<(EQ + T - 1) / T, T, 0, s2>>>(esrc, edst, cursor, col, E);
    cudaEventRecord(evCSR, s2);

    // --- gemm1 (dis-free) on stream 0, concurrent with CSR build ---
    gemm_kernel<128, 64><<<(N + 127) / 128, 128>>>(x, W1, hs1, N);
    cudaStreamWaitEvent(0, evCSR, 0);

    // --- boundary 1: gather(l1) + gemm(l2) fused -> hs2 (pre-scaled) ---
    gather_gemm_kernel<64, true><<<(N + NPB - 1) / NPB, 256>>>(
        rowptr, col, hs1, dis, b1, W2, hs2, N);

    // --- boundary 2: gather(l2) + gemm(l3) fused -> hs3 (pre-scaled) ---
    gather_gemm_kernel<32, false><<<(N + NPB - 1) / NPB, 256>>>(
        rowptr, col, hs2, dis, b2, W3, hs3, N);

    // --- final gather (layer 3) -> out ---
    gather_kernel<32><<<(N * 8 + T - 1) / T, T>>>(rowptr, col, hs3, dis, b3, out, N);

    cudaEventDestroy(evFork);
    cudaEventDestroy(evCSR);
    cudaStreamDestroy(s2);
}